// round 4
// baseline (speedup 1.0000x reference)
#include <cuda_runtime.h>
#include <cuda_bf16.h>
#include <cstdint>

#define B_    64
#define T_    512
#define F_    1024
#define H_    52
#define START_ 50
#define STOP_  51
#define BT_   (B_ * T_)

// K-split partial emit buffers, transposed [b][h][t]
__device__ float g_emitP0[(size_t)B_ * H_ * T_];
__device__ float g_emitP1[(size_t)B_ * H_ * T_];
__device__ float g_diff[B_];

// ---------- packed fp32x2 helpers ----------
__device__ __forceinline__ unsigned long long pk2(float lo, float hi) {
    unsigned long long d;
    asm("mov.b64 %0, {%1, %2};" : "=l"(d) : "r"(__float_as_uint(lo)), "r"(__float_as_uint(hi)));
    return d;
}
__device__ __forceinline__ void upk2(unsigned long long v, float& lo, float& hi) {
    unsigned int a, b;
    asm("mov.b64 {%0, %1}, %2;" : "=r"(a), "=r"(b) : "l"(v));
    lo = __uint_as_float(a); hi = __uint_as_float(b);
}
__device__ __forceinline__ unsigned long long fma2(unsigned long long a, unsigned long long b,
                                                   unsigned long long c) {
    unsigned long long d;
    asm("fma.rn.f32x2 %0, %1, %2, %3;" : "=l"(d) : "l"(a), "l"(b), "l"(c));
    return d;
}
__device__ __forceinline__ unsigned long long add2(unsigned long long a, unsigned long long b) {
    unsigned long long d;
    asm("add.rn.f32x2 %0, %1, %2;" : "=l"(d) : "l"(a), "l"(b));
    return d;
}
__device__ __forceinline__ uint32_t smem_u32(const void* p) {
    uint32_t a;
    asm("{ .reg .u64 t; cvta.to.shared.u64 t, %1; cvt.u32.u64 %0, t; }" : "=r"(a) : "l"(p));
    return a;
}
__device__ __forceinline__ void cpasync4(uint32_t dst, const float* src) {
    asm volatile("cp.async.ca.shared.global [%0], [%1], 4;" :: "r"(dst), "l"(src));
}

// ============================================================
// Kernel 1: emit = features @ W^T + b, K-split by 2.
// grid 256 = 128 row-blocks x 2 K-halves. 256 threads.
// Block tile: 256 rows x 56 cols x 512 K. Thread: 4 rows x 7 pairs.
// Features via cp.async (4B granule) into [row][33] smem; 2 CTAs/SM.
// ============================================================
#define NCH_ 16               // 512 K per block / 32 per chunk
#define SF_ST 33
#define SF_BUFV (256 * SF_ST) // 8448 floats
#define SW_ST 72
#define SW_BUFV (32 * SW_ST)  // 2304 floats
#define GEMM_SMEM_BYTES ((2 * SF_BUFV + 2 * SW_BUFV) * 4)  // 86016 B

__global__ void __launch_bounds__(256, 2)
emit_gemm_kernel(const float* __restrict__ feat, const float* __restrict__ W,
                 const float* __restrict__ bias) {
    extern __shared__ __align__(16) float smem[];
    float* sF = smem;                  // 2 x [256][33]
    float* sW = smem + 2 * SF_BUFV;    // 2 x [32][72]
    const uint32_t sfu = smem_u32(smem);

    const int tid = threadIdx.x;
    const int wid = tid >> 5;
    const int lane = tid & 31;
    const int cg = tid >> 6;       // 0..3 (14 cols each)
    const int rt = tid & 63;       // 0..63
    const int rb = blockIdx.x & 127;
    const int kz = blockIdx.x >> 7;
    const int blockRow = rb * 256;
    const int kbase = kz * 512;

    const int wkk = tid & 31;
    const int whb = tid >> 5;      // 0..7

    unsigned long long acc[4][7];
#pragma unroll
    for (int r = 0; r < 4; r++)
#pragma unroll
        for (int j = 0; j < 7; j++) acc[r][j] = 0ULL;

    float wv[7];

    auto cpF = [&](int c, int b) {
        const int k0 = kbase + c * 32;
        const float* src0 = &feat[(size_t)(blockRow + wid * 32) * F_ + k0 + lane];
        const uint32_t dst0 = sfu + (uint32_t)(b * SF_BUFV + (wid * 32) * SF_ST + lane) * 4;
#pragma unroll
        for (int i = 0; i < 32; i++) {
            cpasync4(dst0 + (uint32_t)(i * SF_ST) * 4, src0 + (size_t)i * F_);
        }
        asm volatile("cp.async.commit_group;" ::: "memory");
    };
    auto ldW = [&](int c) {
        const int k0 = kbase + c * 32;
#pragma unroll
        for (int it = 0; it < 7; it++) {
            int hh = whb + it * 8;             // 0..55
            int hsrc = (hh < H_) ? hh : 0;     // clamp; garbage cols discarded
            wv[it] = W[(size_t)hsrc * F_ + k0 + wkk];
        }
    };
    auto stW = [&](int b) {
        float* w = sW + b * SW_BUFV;
#pragma unroll
        for (int it = 0; it < 7; it++) {
            int hh = whb + it * 8;
            int col = (hh / 14) * 16 + (hh % 14);
            w[wkk * SW_ST + col] = wv[it];
        }
    };
    auto compute = [&](int b) {
        const float* fbase = sF + b * SF_BUFV;
        const float* wbase = sW + b * SW_BUFV;
#pragma unroll 4
        for (int kk = 0; kk < 32; kk++) {
            float f0 = fbase[rt * SF_ST + kk];
            float f1 = fbase[(rt + 64) * SF_ST + kk];
            float f2 = fbase[(rt + 128) * SF_ST + kk];
            float f3 = fbase[(rt + 192) * SF_ST + kk];
            unsigned long long p0 = pk2(f0, f0);
            unsigned long long p1 = pk2(f1, f1);
            unsigned long long p2 = pk2(f2, f2);
            unsigned long long p3 = pk2(f3, f3);
            const float* wrow = wbase + kk * SW_ST + cg * 16;
            ulonglong2 wab = *reinterpret_cast<const ulonglong2*>(wrow);
            ulonglong2 wcd = *reinterpret_cast<const ulonglong2*>(wrow + 4);
            ulonglong2 wef = *reinterpret_cast<const ulonglong2*>(wrow + 8);
            unsigned long long wg = *reinterpret_cast<const unsigned long long*>(wrow + 12);
            acc[0][0] = fma2(p0, wab.x, acc[0][0]);
            acc[1][0] = fma2(p1, wab.x, acc[1][0]);
            acc[2][0] = fma2(p2, wab.x, acc[2][0]);
            acc[3][0] = fma2(p3, wab.x, acc[3][0]);
            acc[0][1] = fma2(p0, wab.y, acc[0][1]);
            acc[1][1] = fma2(p1, wab.y, acc[1][1]);
            acc[2][1] = fma2(p2, wab.y, acc[2][1]);
            acc[3][1] = fma2(p3, wab.y, acc[3][1]);
            acc[0][2] = fma2(p0, wcd.x, acc[0][2]);
            acc[1][2] = fma2(p1, wcd.x, acc[1][2]);
            acc[2][2] = fma2(p2, wcd.x, acc[2][2]);
            acc[3][2] = fma2(p3, wcd.x, acc[3][2]);
            acc[0][3] = fma2(p0, wcd.y, acc[0][3]);
            acc[1][3] = fma2(p1, wcd.y, acc[1][3]);
            acc[2][3] = fma2(p2, wcd.y, acc[2][3]);
            acc[3][3] = fma2(p3, wcd.y, acc[3][3]);
            acc[0][4] = fma2(p0, wef.x, acc[0][4]);
            acc[1][4] = fma2(p1, wef.x, acc[1][4]);
            acc[2][4] = fma2(p2, wef.x, acc[2][4]);
            acc[3][4] = fma2(p3, wef.x, acc[3][4]);
            acc[0][5] = fma2(p0, wef.y, acc[0][5]);
            acc[1][5] = fma2(p1, wef.y, acc[1][5]);
            acc[2][5] = fma2(p2, wef.y, acc[2][5]);
            acc[3][5] = fma2(p3, wef.y, acc[3][5]);
            acc[0][6] = fma2(p0, wg, acc[0][6]);
            acc[1][6] = fma2(p1, wg, acc[1][6]);
            acc[2][6] = fma2(p2, wg, acc[2][6]);
            acc[3][6] = fma2(p3, wg, acc[3][6]);
        }
    };

    // prologue
    cpF(0, 0);
    ldW(0);
    stW(0);
    ldW(1);
    cpF(1, 1);
    asm volatile("cp.async.wait_group 1;" ::: "memory");  // chunk 0 done
    __syncthreads();

#pragma unroll 1
    for (int c = 0; c < NCH_; c++) {
        const int buf = c & 1;
        if (c + 1 < NCH_) stW(buf ^ 1);    // wv holds W(c+1)
        if (c + 2 < NCH_) ldW(c + 2);
        compute(buf);
        __syncthreads();                    // all readers of fbuf[buf] done
        if (c + 2 < NCH_) {
            cpF(c + 2, buf);
            asm volatile("cp.async.wait_group 1;" ::: "memory");  // c+1 done
        } else {
            asm volatile("cp.async.wait_group 0;" ::: "memory");
        }
        __syncthreads();                    // c+1 data + W STS visible
    }

    // epilogue: store transposed into this K-half's partial buffer
    float* outP = (kz == 0) ? g_emitP0 : g_emitP1;
#pragma unroll
    for (int r = 0; r < 4; r++) {
        int row = blockRow + rt + r * 64;   // global (b*T + t)
        int b = row >> 9;
        int t = row & 511;
        size_t bbase = (size_t)b * (H_ * T_);
#pragma unroll
        for (int j = 0; j < 7; j++) {
            int col = cg * 14 + 2 * j;
            if (col + 1 < H_) {
                float lo, hi;
                upk2(acc[r][j], lo, hi);
                if (kz == 0) { lo += __ldg(&bias[col]); hi += __ldg(&bias[col + 1]); }
                outP[bbase + (size_t)col * T_ + t] = lo;
                outP[bbase + (size_t)(col + 1) * T_ + t] = hi;
            }
        }
    }
}

// ============================================================
// Kernel 2: CRF forward — ONE WARP handles TWO batches (interleaved
// to fill latency stalls). 32 blocks x 32 threads. Lane owns states
// (lane, lane+32) for both batches. Prob-space, renorm every 4 steps.
// Emit = P0 + P1 (K-split partials summed here).
// ============================================================
__global__ void __launch_bounds__(32, 1)
crf_scan_kernel(const float* __restrict__ transition, const float* __restrict__ masks,
                const int* __restrict__ tags) {
    const int bb = blockIdx.x;           // 0..31
    const int lane = threadIdx.x;
    const int h0 = lane;
    const int h1 = lane + 32;
    const bool act1 = (h1 < H_);
    const unsigned FULL = 0xFFFFFFFFu;
    const int baseA = (2 * bb) * T_;
    const int baseB = baseA + T_;

    __shared__ __align__(16) float pd[2][2][56];   // [batch][buf][state]

    const float* PA0 = &g_emitP0[(size_t)(2 * bb) * (H_ * T_)];
    const float* PA1 = &g_emitP1[(size_t)(2 * bb) * (H_ * T_)];
    const float* PB0 = PA0 + H_ * T_;
    const float* PB1 = PA1 + H_ * T_;

    // ---- gold scores (both batches) ----
    float golA = 0.0f, msA = 0.0f, golB = 0.0f, msB = 0.0f;
    for (int t = lane; t < T_; t += 32) {
        {
            float mk = masks[baseA + t];
            int tg = tags[baseA + t];
            int pv = (t == 0) ? START_ : tags[baseA + t - 1];
            golA += mk * (PA0[(size_t)tg * T_ + t] + PA1[(size_t)tg * T_ + t] +
                          transition[tg * H_ + pv]);
            msA += mk;
        }
        {
            float mk = masks[baseB + t];
            int tg = tags[baseB + t];
            int pv = (t == 0) ? START_ : tags[baseB + t - 1];
            golB += mk * (PB0[(size_t)tg * T_ + t] + PB1[(size_t)tg * T_ + t] +
                          transition[tg * H_ + pv]);
            msB += mk;
        }
    }
#pragma unroll
    for (int s = 16; s > 0; s >>= 1) {
        golA += __shfl_xor_sync(FULL, golA, s);
        msA  += __shfl_xor_sync(FULL, msA, s);
        golB += __shfl_xor_sync(FULL, golB, s);
        msB  += __shfl_xor_sync(FULL, msB, s);
    }
    {
        int lpA = (int)(msA + 0.5f);
        int ltA = (lpA > 0) ? tags[baseA + lpA - 1] : START_;
        golA += transition[STOP_ * H_ + ltA];
        int lpB = (int)(msB + 0.5f);
        int ltB = (lpB > 0) ? tags[baseB + lpB - 1] : START_;
        golB += transition[STOP_ * H_ + ltB];
    }

    // ---- E rows (shared by both batches) ----
    unsigned long long E0[26], E1[26];
    {
        const float* r0 = &transition[h0 * H_];
        const float* r1 = &transition[(act1 ? h1 : 0) * H_];
#pragma unroll
        for (int j = 0; j < 26; j++) {
            E0[j] = pk2(__expf(r0[2 * j]), __expf(r0[2 * j + 1]));
            E1[j] = pk2(__expf(r1[2 * j]), __expf(r1[2 * j + 1]));
        }
    }

    // ---- init ----
    pd[0][0][h0] = (h0 == START_) ? 1.0f : 0.0f;
    pd[1][0][h0] = (h0 == START_) ? 1.0f : 0.0f;
    if (act1) {
        pd[0][0][h1] = (h1 == START_) ? 1.0f : 0.0f;
        pd[1][0][h1] = (h1 == START_) ? 1.0f : 0.0f;
    }
    float pA0 = (h0 == START_) ? 1.0f : 0.0f;
    float pA1 = (h1 == START_) ? 1.0f : 0.0f;
    float pB0 = pA0, pB1 = pA1;
    float offA = 0.0f, offB = 0.0f;

    // ---- emit streams (per batch, per state, per partial) ----
    const float* eA0a = PA0 + (size_t)h0 * T_;
    const float* eA0b = PA1 + (size_t)h0 * T_;
    const float* eA1a = PA0 + (size_t)(act1 ? h1 : 0) * T_;
    const float* eA1b = PA1 + (size_t)(act1 ? h1 : 0) * T_;
    const float* eB0a = PB0 + (size_t)h0 * T_;
    const float* eB0b = PB1 + (size_t)h0 * T_;
    const float* eB1a = PB0 + (size_t)(act1 ? h1 : 0) * T_;
    const float* eB1b = PB1 + (size_t)(act1 ? h1 : 0) * T_;
    const float4* mAp = reinterpret_cast<const float4*>(&masks[baseA]);
    const float4* mBp = reinterpret_cast<const float4*>(&masks[baseB]);

    float eCA0[4], eCA1[4], eCB0[4], eCB1[4];
    float4 mkA4, mkB4;
    {   // prime block 0
        float4 a, b;
        a = *reinterpret_cast<const float4*>(eA0a); b = *reinterpret_cast<const float4*>(eA0b);
        eCA0[0] = __expf(a.x + b.x); eCA0[1] = __expf(a.y + b.y);
        eCA0[2] = __expf(a.z + b.z); eCA0[3] = __expf(a.w + b.w);
        a = *reinterpret_cast<const float4*>(eA1a); b = *reinterpret_cast<const float4*>(eA1b);
        eCA1[0] = __expf(a.x + b.x); eCA1[1] = __expf(a.y + b.y);
        eCA1[2] = __expf(a.z + b.z); eCA1[3] = __expf(a.w + b.w);
        a = *reinterpret_cast<const float4*>(eB0a); b = *reinterpret_cast<const float4*>(eB0b);
        eCB0[0] = __expf(a.x + b.x); eCB0[1] = __expf(a.y + b.y);
        eCB0[2] = __expf(a.z + b.z); eCB0[3] = __expf(a.w + b.w);
        a = *reinterpret_cast<const float4*>(eB1a); b = *reinterpret_cast<const float4*>(eB1b);
        eCB1[0] = __expf(a.x + b.x); eCB1[1] = __expf(a.y + b.y);
        eCB1[2] = __expf(a.z + b.z); eCB1[3] = __expf(a.w + b.w);
        mkA4 = mAp[0]; mkB4 = mBp[0];
    }
    __syncwarp();

    int cur = 0;
    const int NB = T_ / 4;  // 128
    for (int tb = 0; tb < NB; tb++) {
        // issue next block's loads early (consumed at the bottom => ~4 steps of slack)
        float4 lA0a, lA0b, lA1a, lA1b, lB0a, lB0b, lB1a, lB1b, lmA, lmB;
        const bool hv = (tb + 1 < NB);
        if (hv) {
            const int o = (tb + 1) * 4;
            lA0a = *reinterpret_cast<const float4*>(eA0a + o);
            lA0b = *reinterpret_cast<const float4*>(eA0b + o);
            lA1a = *reinterpret_cast<const float4*>(eA1a + o);
            lA1b = *reinterpret_cast<const float4*>(eA1b + o);
            lB0a = *reinterpret_cast<const float4*>(eB0a + o);
            lB0b = *reinterpret_cast<const float4*>(eB0b + o);
            lB1a = *reinterpret_cast<const float4*>(eB1a + o);
            lB1b = *reinterpret_cast<const float4*>(eB1b + o);
            lmA = mAp[tb + 1]; lmB = mBp[tb + 1];
        }
        float mkA[4] = {mkA4.x, mkA4.y, mkA4.z, mkA4.w};
        float mkB[4] = {mkB4.x, mkB4.y, mkB4.z, mkB4.w};

        float rinvA = 1.0f, rinvB = 1.0f;
        if (tb) {
            float rA = __shfl_sync(FULL, pA0, 0);
            float rB = __shfl_sync(FULL, pB0, 0);
            rinvA = 1.0f / rA; offA += __logf(rA);
            rinvB = 1.0f / rB; offB += __logf(rB);
        }

#pragma unroll
        for (int s = 0; s < 4; s++) {
            const float* pa = pd[0][cur];
            const float* pb = pd[1][cur];
            unsigned long long aA0 = 0, aA1 = 0, aA2 = 0, aA3 = 0;
            unsigned long long cA0 = 0, cA1 = 0, cA2 = 0, cA3 = 0;
            unsigned long long aB0 = 0, aB1 = 0, aB2 = 0, aB3 = 0;
            unsigned long long cB0 = 0, cB1 = 0, cB2 = 0, cB3 = 0;
#pragma unroll
            for (int q = 0; q < 13; q++) {
                ulonglong2 uA = *reinterpret_cast<const ulonglong2*>(&pa[4 * q]);
                ulonglong2 uB = *reinterpret_cast<const ulonglong2*>(&pb[4 * q]);
                if (q & 1) {
                    aA2 = fma2(E0[2 * q], uA.x, aA2); aA3 = fma2(E0[2 * q + 1], uA.y, aA3);
                    cA2 = fma2(E1[2 * q], uA.x, cA2); cA3 = fma2(E1[2 * q + 1], uA.y, cA3);
                    aB2 = fma2(E0[2 * q], uB.x, aB2); aB3 = fma2(E0[2 * q + 1], uB.y, aB3);
                    cB2 = fma2(E1[2 * q], uB.x, cB2); cB3 = fma2(E1[2 * q + 1], uB.y, cB3);
                } else {
                    aA0 = fma2(E0[2 * q], uA.x, aA0); aA1 = fma2(E0[2 * q + 1], uA.y, aA1);
                    cA0 = fma2(E1[2 * q], uA.x, cA0); cA1 = fma2(E1[2 * q + 1], uA.y, cA1);
                    aB0 = fma2(E0[2 * q], uB.x, aB0); aB1 = fma2(E0[2 * q + 1], uB.y, aB1);
                    cB0 = fma2(E1[2 * q], uB.x, cB0); cB1 = fma2(E1[2 * q + 1], uB.y, cB1);
                }
            }
            unsigned long long sA = add2(add2(aA0, aA1), add2(aA2, aA3));
            unsigned long long sAc = add2(add2(cA0, cA1), add2(cA2, cA3));
            unsigned long long sB = add2(add2(aB0, aB1), add2(aB2, aB3));
            unsigned long long sBc = add2(add2(cB0, cB1), add2(cB2, cB3));
            float x, y;
            upk2(sA, x, y);  float SA0 = x + y;
            upk2(sAc, x, y); float SA1 = x + y;
            upk2(sB, x, y);  float SB0 = x + y;
            upk2(sBc, x, y); float SB1 = x + y;
            bool onA = (mkA[s] > 0.5f), onB = (mkB[s] > 0.5f);
            float nA0 = onA ? SA0 * eCA0[s] : pA0;
            float nA1 = onA ? SA1 * eCA1[s] : pA1;
            float nB0 = onB ? SB0 * eCB0[s] : pB0;
            float nB1 = onB ? SB1 * eCB1[s] : pB1;
            if (s == 0) { nA0 *= rinvA; nA1 *= rinvA; nB0 *= rinvB; nB1 *= rinvB; }
            pd[0][cur ^ 1][h0] = nA0;
            pd[1][cur ^ 1][h0] = nB0;
            if (act1) { pd[0][cur ^ 1][h1] = nA1; pd[1][cur ^ 1][h1] = nB1; }
            pA0 = nA0; pA1 = nA1; pB0 = nB0; pB1 = nB1;
            cur ^= 1;
            __syncwarp();
        }

        if (hv) {  // combine partials + exp for next block (loads landed long ago)
            eCA0[0] = __expf(lA0a.x + lA0b.x); eCA0[1] = __expf(lA0a.y + lA0b.y);
            eCA0[2] = __expf(lA0a.z + lA0b.z); eCA0[3] = __expf(lA0a.w + lA0b.w);
            eCA1[0] = __expf(lA1a.x + lA1b.x); eCA1[1] = __expf(lA1a.y + lA1b.y);
            eCA1[2] = __expf(lA1a.z + lA1b.z); eCA1[3] = __expf(lA1a.w + lA1b.w);
            eCB0[0] = __expf(lB0a.x + lB0b.x); eCB0[1] = __expf(lB0a.y + lB0b.y);
            eCB0[2] = __expf(lB0a.z + lB0b.z); eCB0[3] = __expf(lB0a.w + lB0b.w);
            eCB1[0] = __expf(lB1a.x + lB1b.x); eCB1[1] = __expf(lB1a.y + lB1b.y);
            eCB1[2] = __expf(lB1a.z + lB1b.z); eCB1[3] = __expf(lB1a.w + lB1b.w);
            mkA4 = lmA; mkB4 = lmB;
        }
    }

    // ---- final ----
    float es0 = __expf(transition[STOP_ * H_ + h0]);
    float es1 = act1 ? __expf(transition[STOP_ * H_ + h1]) : 0.0f;
    float termA = pA0 * es0 + (act1 ? pA1 * es1 : 0.0f);
    float termB = pB0 * es0 + (act1 ? pB1 * es1 : 0.0f);
#pragma unroll
    for (int s = 16; s > 0; s >>= 1) {
        termA += __shfl_xor_sync(FULL, termA, s);
        termB += __shfl_xor_sync(FULL, termB, s);
    }
    if (lane == 0) {
        g_diff[2 * bb]     = offA + __logf(termA) - golA;
        g_diff[2 * bb + 1] = offB + __logf(termB) - golB;
    }
}

// ============================================================
// Kernel 3: mean over batches
// ============================================================
__global__ void __launch_bounds__(64)
finalize_kernel(float* __restrict__ out) {
    __shared__ float red[64];
    int tid = threadIdx.x;
    red[tid] = g_diff[tid];
    __syncthreads();
    for (int s = 32; s > 0; s >>= 1) { if (tid < s) red[tid] += red[tid + s]; __syncthreads(); }
    if (tid == 0) out[0] = red[0] * (1.0f / (float)B_);
}

// ============================================================
// launch
// ============================================================
extern "C" void kernel_launch(void* const* d_in, const int* in_sizes, int n_in,
                              void* d_out, int out_size) {
    const float* feat  = (const float*)d_in[0];
    const float* W     = (const float*)d_in[1];
    const float* bias  = (const float*)d_in[2];
    const float* trans = (const float*)d_in[3];
    const float* masks = (const float*)d_in[4];
    const int*   tags  = (const int*)d_in[5];
    float* out = (float*)d_out;

    cudaFuncSetAttribute(emit_gemm_kernel,
                         cudaFuncAttributeMaxDynamicSharedMemorySize, GEMM_SMEM_BYTES);

    emit_gemm_kernel<<<256, 256, GEMM_SMEM_BYTES>>>(feat, W, bias);
    crf_scan_kernel<<<B_ / 2, 32>>>(trans, masks, tags);
    finalize_kernel<<<1, 64>>>(out);
}

// round 5
// speedup vs baseline: 1.2773x; 1.2773x over previous
#include <cuda_runtime.h>
#include <cuda_bf16.h>
#include <cstdint>

#define B_    64
#define T_    512
#define F_    1024
#define H_    52
#define START_ 50
#define STOP_  51
#define BT_   (B_ * T_)

__device__ float g_emitT[(size_t)B_ * H_ * T_]; // emit transposed [b][h][t]
__device__ float g_diff[B_];

// ---------- packed fp32x2 helpers ----------
__device__ __forceinline__ unsigned long long pk2(float lo, float hi) {
    unsigned long long d;
    asm("mov.b64 %0, {%1, %2};" : "=l"(d) : "r"(__float_as_uint(lo)), "r"(__float_as_uint(hi)));
    return d;
}
__device__ __forceinline__ void upk2(unsigned long long v, float& lo, float& hi) {
    unsigned int a, b;
    asm("mov.b64 {%0, %1}, %2;" : "=r"(a), "=r"(b) : "l"(v));
    lo = __uint_as_float(a); hi = __uint_as_float(b);
}
__device__ __forceinline__ unsigned long long fma2(unsigned long long a, unsigned long long b,
                                                   unsigned long long c) {
    unsigned long long d;
    asm("fma.rn.f32x2 %0, %1, %2, %3;" : "=l"(d) : "l"(a), "l"(b), "l"(c));
    return d;
}
__device__ __forceinline__ unsigned long long add2(unsigned long long a, unsigned long long b) {
    unsigned long long d;
    asm("add.rn.f32x2 %0, %1, %2;" : "=l"(d) : "l"(a), "l"(b));
    return d;
}

// ============================================================
// Kernel 1: emit = features @ W^T + b   (M=32768, N=52, K=1024)
// EXACT Round-1 configuration (best measured: 99.7us), except the
// epilogue stores TRANSPOSED to g_emitT[b][h][t] (coalesced: warp
// lanes span consecutive t).
// ============================================================
__global__ void __launch_bounds__(256, 1)
emit_gemm_kernel(const float* __restrict__ feat, const float* __restrict__ W,
                 const float* __restrict__ bias) {
    __shared__ float sF[32 * 257];  // [kk][row], stride 257
    __shared__ float sW[32 * 58];   // [kk][h],   stride 58

    const int tid = threadIdx.x;
    const int cg = tid >> 6;       // 0..3  (14 cols each)
    const int rt = tid & 63;       // 0..63
    const int blockRow = blockIdx.x * 256;

    const int lrow = tid >> 3;     // 0..31
    const int ljj  = tid & 7;      // 0..7
    const int wkk  = tid & 31;
    const int whb  = tid >> 5;     // 0..7

    unsigned long long acc[4][7];
#pragma unroll
    for (int r = 0; r < 4; r++)
#pragma unroll
        for (int j = 0; j < 7; j++) acc[r][j] = 0ULL;

    float4 fv[8];
    float  wv[7];

    auto load_chunk = [&](int k0) {
#pragma unroll
        for (int it = 0; it < 8; it++) {
            int row = lrow + it * 32;
            fv[it] = *reinterpret_cast<const float4*>(
                &feat[(size_t)(blockRow + row) * F_ + k0 + ljj * 4]);
        }
#pragma unroll
        for (int it = 0; it < 7; it++) {
            int hh = whb + it * 8;  // 0..55
            wv[it] = (hh < H_) ? W[(size_t)hh * F_ + k0 + wkk] : 0.0f;
        }
    };
    auto store_chunk = [&]() {
#pragma unroll
        for (int it = 0; it < 8; it++) {
            int row = lrow + it * 32;
            sF[(ljj * 4 + 0) * 257 + row] = fv[it].x;
            sF[(ljj * 4 + 1) * 257 + row] = fv[it].y;
            sF[(ljj * 4 + 2) * 257 + row] = fv[it].z;
            sF[(ljj * 4 + 3) * 257 + row] = fv[it].w;
        }
#pragma unroll
        for (int it = 0; it < 7; it++) sW[wkk * 58 + whb + it * 8] = wv[it];
    };

    load_chunk(0);
    for (int k0 = 0; k0 < F_; k0 += 32) {
        __syncthreads();
        store_chunk();
        __syncthreads();
        if (k0 + 32 < F_) load_chunk(k0 + 32);

#pragma unroll 4
        for (int kk = 0; kk < 32; kk++) {
            float f0 = sF[kk * 257 + rt];
            float f1 = sF[kk * 257 + rt + 64];
            float f2 = sF[kk * 257 + rt + 128];
            float f3 = sF[kk * 257 + rt + 192];
            unsigned long long p0 = pk2(f0, f0);
            unsigned long long p1 = pk2(f1, f1);
            unsigned long long p2 = pk2(f2, f2);
            unsigned long long p3 = pk2(f3, f3);
#pragma unroll
            for (int j = 0; j < 7; j++) {
                unsigned long long w2 = *reinterpret_cast<const unsigned long long*>(
                    &sW[kk * 58 + cg * 14 + 2 * j]);
                acc[0][j] = fma2(p0, w2, acc[0][j]);
                acc[1][j] = fma2(p1, w2, acc[1][j]);
                acc[2][j] = fma2(p2, w2, acc[2][j]);
                acc[3][j] = fma2(p3, w2, acc[3][j]);
            }
        }
    }

    // epilogue: + bias, store transposed (each store coalesced across warp)
#pragma unroll
    for (int r = 0; r < 4; r++) {
        int row = blockRow + rt + r * 64;   // global (b*T + t)
        int b = row >> 9;
        int t = row & 511;
        size_t bbase = (size_t)b * (H_ * T_);
#pragma unroll
        for (int j = 0; j < 7; j++) {
            int col = cg * 14 + 2 * j;
            if (col + 1 < H_) {
                float lo, hi;
                upk2(acc[r][j], lo, hi);
                lo += __ldg(&bias[col]);
                hi += __ldg(&bias[col + 1]);
                g_emitT[bbase + (size_t)col * T_ + t] = lo;
                g_emitT[bbase + (size_t)(col + 1) * T_ + t] = hi;
            }
        }
    }
}

// ============================================================
// Kernel 2: CRF forward — SINGLE WARP per batch, REGISTER-ONLY state.
// Lane owns dest states (lane, lane+32). Broadcast of p via __shfl_sync:
// no shared memory, no barriers, no load latency on the critical path.
// E2[src] = (exp(trans[d0][src]), exp(trans[d1][src])) so one fma2
// updates both dests. Renorm by p[0] every 4 steps.
// ============================================================
__global__ void __launch_bounds__(32, 1)
crf_scan_kernel(const float* __restrict__ transition, const float* __restrict__ masks,
                const int* __restrict__ tags) {
    const int b = blockIdx.x;
    const int lane = threadIdx.x;
    const int d0 = lane;
    const int d1 = lane + 32;
    const bool act1 = (d1 < H_);   // lane < 20
    const int base = b * T_;
    const unsigned FULL = 0xFFFFFFFFu;

    const float* embB = &g_emitT[(size_t)b * (H_ * T_)];

    // ---- gold score ----
    float gold = 0.0f, msum = 0.0f;
    for (int t = lane; t < T_; t += 32) {
        float mk = masks[base + t];
        int tg = tags[base + t];
        int pv = (t == 0) ? START_ : tags[base + t - 1];
        gold += mk * (embB[(size_t)tg * T_ + t] + transition[tg * H_ + pv]);
        msum += mk;
    }
#pragma unroll
    for (int s = 16; s > 0; s >>= 1) {
        gold += __shfl_xor_sync(FULL, gold, s);
        msum += __shfl_xor_sync(FULL, msum, s);
    }
    int last_pos = (int)(msum + 0.5f);
    int last_tag = (last_pos > 0) ? tags[base + last_pos - 1] : START_;
    gold += transition[STOP_ * H_ + last_tag];

    // ---- E2[src] = (exp(trans[d0][src]), exp(trans[d1][src])) ----
    unsigned long long E2[52];
    {
        const float* r0 = &transition[d0 * H_];
        const float* r1 = &transition[(act1 ? d1 : 0) * H_];
#pragma unroll
        for (int s = 0; s < H_; s++) E2[s] = pk2(__expf(r0[s]), __expf(r1[s]));
    }

    // ---- init: p = onehot(START) ----
    float p0 = 0.0f;                               // d0 in 0..31 < START
    float p1 = (act1 && d1 == START_) ? 1.0f : 0.0f;
    float offset = 0.0f;

    // ---- emit/mask pipeline (4-step blocks, ~8-12 step lookahead) ----
    const float* e0 = embB + (size_t)d0 * T_;
    const float* e1 = embB + (size_t)(act1 ? d1 : 0) * T_;
    const float4* m4 = reinterpret_cast<const float4*>(&masks[base]);

    float eC0[4], eC1[4];
    float4 rn0, rn1, rrn0, rrn1, mkC, mkN, mkN2;
    {
        float4 a = *reinterpret_cast<const float4*>(e0);
        float4 c = *reinterpret_cast<const float4*>(e1);
        eC0[0] = __expf(a.x); eC0[1] = __expf(a.y); eC0[2] = __expf(a.z); eC0[3] = __expf(a.w);
        eC1[0] = __expf(c.x); eC1[1] = __expf(c.y); eC1[2] = __expf(c.z); eC1[3] = __expf(c.w);
        rn0  = *reinterpret_cast<const float4*>(e0 + 4);
        rn1  = *reinterpret_cast<const float4*>(e1 + 4);
        rrn0 = *reinterpret_cast<const float4*>(e0 + 8);
        rrn1 = *reinterpret_cast<const float4*>(e1 + 8);
        mkC = m4[0]; mkN = m4[1]; mkN2 = m4[2];
    }

    const int NB = T_ / 4;  // 128
    for (int tb = 0; tb < NB; tb++) {
        float4 l0, l1, lm;
        const bool hv = (tb + 3 < NB);
        if (hv) {
            l0 = *reinterpret_cast<const float4*>(e0 + (tb + 3) * 4);
            l1 = *reinterpret_cast<const float4*>(e1 + (tb + 3) * 4);
            lm = m4[tb + 3];
        }
        float eN0[4], eN1[4];
        eN0[0] = __expf(rn0.x); eN0[1] = __expf(rn0.y); eN0[2] = __expf(rn0.z); eN0[3] = __expf(rn0.w);
        eN1[0] = __expf(rn1.x); eN1[1] = __expf(rn1.y); eN1[2] = __expf(rn1.z); eN1[3] = __expf(rn1.w);

        float rinv = 1.0f;
        if (tb) {
            float r = __shfl_sync(FULL, p0, 0);   // p[state 0]
            rinv = 1.0f / r;
            offset += __logf(r);
        }
        float mk[4] = {mkC.x, mkC.y, mkC.z, mkC.w};

#pragma unroll
        for (int s = 0; s < 4; s++) {
            unsigned long long A0 = 0ULL, A1 = 0ULL, A2 = 0ULL, A3 = 0ULL;
#pragma unroll
            for (int q = 0; q < 32; q++) {
                float v = __shfl_sync(FULL, p0, q);
                unsigned long long v2 = pk2(v, v);
                switch (q & 3) {
                    case 0: A0 = fma2(E2[q], v2, A0); break;
                    case 1: A1 = fma2(E2[q], v2, A1); break;
                    case 2: A2 = fma2(E2[q], v2, A2); break;
                    default: A3 = fma2(E2[q], v2, A3); break;
                }
            }
#pragma unroll
            for (int q = 0; q < 20; q++) {
                float v = __shfl_sync(FULL, p1, q);
                unsigned long long v2 = pk2(v, v);
                switch (q & 3) {
                    case 0: A0 = fma2(E2[32 + q], v2, A0); break;
                    case 1: A1 = fma2(E2[32 + q], v2, A1); break;
                    case 2: A2 = fma2(E2[32 + q], v2, A2); break;
                    default: A3 = fma2(E2[32 + q], v2, A3); break;
                }
            }
            unsigned long long S2 = add2(add2(A0, A1), add2(A2, A3));
            float S0, S1;
            upk2(S2, S0, S1);
            bool on = (mk[s] > 0.5f);
            float n0 = on ? S0 * eC0[s] : p0;
            float n1 = on ? S1 * eC1[s] : p1;
            if (s == 0) { n0 *= rinv; n1 *= rinv; }
            p0 = n0; p1 = n1;
        }

        eC0[0] = eN0[0]; eC0[1] = eN0[1]; eC0[2] = eN0[2]; eC0[3] = eN0[3];
        eC1[0] = eN1[0]; eC1[1] = eN1[1]; eC1[2] = eN1[2]; eC1[3] = eN1[3];
        rn0 = rrn0; rn1 = rrn1;
        mkC = mkN; mkN = mkN2;
        if (hv) { rrn0 = l0; rrn1 = l1; mkN2 = lm; }
    }

    // ---- final: fwd = offset + log(sum_h p[h] * exp(trans[STOP,h])) ----
    float term = p0 * __expf(transition[STOP_ * H_ + d0]);
    if (act1) term += p1 * __expf(transition[STOP_ * H_ + d1]);
#pragma unroll
    for (int s = 16; s > 0; s >>= 1) term += __shfl_xor_sync(FULL, term, s);
    if (lane == 0) {
        float fwd = offset + __logf(term);
        g_diff[b] = fwd - gold;
    }
}

// ============================================================
// Kernel 3: mean over batches
// ============================================================
__global__ void __launch_bounds__(64)
finalize_kernel(float* __restrict__ out) {
    __shared__ float red[64];
    int tid = threadIdx.x;
    red[tid] = g_diff[tid];
    __syncthreads();
    for (int s = 32; s > 0; s >>= 1) { if (tid < s) red[tid] += red[tid + s]; __syncthreads(); }
    if (tid == 0) out[0] = red[0] * (1.0f / (float)B_);
}

// ============================================================
// launch
// ============================================================
extern "C" void kernel_launch(void* const* d_in, const int* in_sizes, int n_in,
                              void* d_out, int out_size) {
    const float* feat  = (const float*)d_in[0];
    const float* W     = (const float*)d_in[1];
    const float* bias  = (const float*)d_in[2];
    const float* trans = (const float*)d_in[3];
    const float* masks = (const float*)d_in[4];
    const int*   tags  = (const int*)d_in[5];
    float* out = (float*)d_out;

    emit_gemm_kernel<<<128, 256>>>(feat, W, bias);
    crf_scan_kernel<<<B_, 32>>>(trans, masks, tags);
    finalize_kernel<<<1, 64>>>(out);
}

// round 6
// speedup vs baseline: 1.3708x; 1.0732x over previous
#include <cuda_runtime.h>
#include <cuda_bf16.h>
#include <cstdint>

#define B_    64
#define T_    512
#define F_    1024
#define H_    52
#define HP_   56        // padded states (multiple of 14)
#define START_ 50
#define STOP_  51
#define BT_   (B_ * T_)

__device__ float g_emitT[(size_t)B_ * H_ * T_]; // emit transposed [b][h][t]
__device__ float g_diff[B_];

// ---------- packed fp32x2 helpers ----------
__device__ __forceinline__ unsigned long long pk2(float lo, float hi) {
    unsigned long long d;
    asm("mov.b64 %0, {%1, %2};" : "=l"(d) : "r"(__float_as_uint(lo)), "r"(__float_as_uint(hi)));
    return d;
}
__device__ __forceinline__ void upk2(unsigned long long v, float& lo, float& hi) {
    unsigned int a, b;
    asm("mov.b64 {%0, %1}, %2;" : "=r"(a), "=r"(b) : "l"(v));
    lo = __uint_as_float(a); hi = __uint_as_float(b);
}
__device__ __forceinline__ unsigned long long fma2(unsigned long long a, unsigned long long b,
                                                   unsigned long long c) {
    unsigned long long d;
    asm("fma.rn.f32x2 %0, %1, %2, %3;" : "=l"(d) : "l"(a), "l"(b), "l"(c));
    return d;
}
__device__ __forceinline__ unsigned long long add2(unsigned long long a, unsigned long long b) {
    unsigned long long d;
    asm("add.rn.f32x2 %0, %1, %2;" : "=l"(d) : "l"(a), "l"(b));
    return d;
}

// ============================================================
// Kernel 1: emit GEMM — frozen at best-measured config (R5: 91.4us).
// ============================================================
__global__ void __launch_bounds__(256, 1)
emit_gemm_kernel(const float* __restrict__ feat, const float* __restrict__ W,
                 const float* __restrict__ bias) {
    __shared__ float sF[32 * 257];
    __shared__ float sW[32 * 58];

    const int tid = threadIdx.x;
    const int cg = tid >> 6;
    const int rt = tid & 63;
    const int blockRow = blockIdx.x * 256;

    const int lrow = tid >> 3;
    const int ljj  = tid & 7;
    const int wkk  = tid & 31;
    const int whb  = tid >> 5;

    unsigned long long acc[4][7];
#pragma unroll
    for (int r = 0; r < 4; r++)
#pragma unroll
        for (int j = 0; j < 7; j++) acc[r][j] = 0ULL;

    float4 fv[8];
    float  wv[7];

    auto load_chunk = [&](int k0) {
#pragma unroll
        for (int it = 0; it < 8; it++) {
            int row = lrow + it * 32;
            fv[it] = *reinterpret_cast<const float4*>(
                &feat[(size_t)(blockRow + row) * F_ + k0 + ljj * 4]);
        }
#pragma unroll
        for (int it = 0; it < 7; it++) {
            int hh = whb + it * 8;
            wv[it] = (hh < H_) ? W[(size_t)hh * F_ + k0 + wkk] : 0.0f;
        }
    };
    auto store_chunk = [&]() {
#pragma unroll
        for (int it = 0; it < 8; it++) {
            int row = lrow + it * 32;
            sF[(ljj * 4 + 0) * 257 + row] = fv[it].x;
            sF[(ljj * 4 + 1) * 257 + row] = fv[it].y;
            sF[(ljj * 4 + 2) * 257 + row] = fv[it].z;
            sF[(ljj * 4 + 3) * 257 + row] = fv[it].w;
        }
#pragma unroll
        for (int it = 0; it < 7; it++) sW[wkk * 58 + whb + it * 8] = wv[it];
    };

    load_chunk(0);
    for (int k0 = 0; k0 < F_; k0 += 32) {
        __syncthreads();
        store_chunk();
        __syncthreads();
        if (k0 + 32 < F_) load_chunk(k0 + 32);

#pragma unroll 4
        for (int kk = 0; kk < 32; kk++) {
            float f0 = sF[kk * 257 + rt];
            float f1 = sF[kk * 257 + rt + 64];
            float f2 = sF[kk * 257 + rt + 128];
            float f3 = sF[kk * 257 + rt + 192];
            unsigned long long p0 = pk2(f0, f0);
            unsigned long long p1 = pk2(f1, f1);
            unsigned long long p2 = pk2(f2, f2);
            unsigned long long p3 = pk2(f3, f3);
#pragma unroll
            for (int j = 0; j < 7; j++) {
                unsigned long long w2 = *reinterpret_cast<const unsigned long long*>(
                    &sW[kk * 58 + cg * 14 + 2 * j]);
                acc[0][j] = fma2(p0, w2, acc[0][j]);
                acc[1][j] = fma2(p1, w2, acc[1][j]);
                acc[2][j] = fma2(p2, w2, acc[2][j]);
                acc[3][j] = fma2(p3, w2, acc[3][j]);
            }
        }
    }

#pragma unroll
    for (int r = 0; r < 4; r++) {
        int row = blockRow + rt + r * 64;
        int b = row >> 9;
        int t = row & 511;
        size_t bbase = (size_t)b * (H_ * T_);
#pragma unroll
        for (int j = 0; j < 7; j++) {
            int col = cg * 14 + 2 * j;
            if (col + 1 < H_) {
                float lo, hi;
                upk2(acc[r][j], lo, hi);
                lo += __ldg(&bias[col]);
                hi += __ldg(&bias[col + 1]);
                g_emitT[bbase + (size_t)col * T_ + t] = lo;
                g_emitT[bbase + (size_t)(col + 1) * T_ + t] = hi;
            }
        }
    }
}

// ============================================================
// Kernel 2: CRF forward — 4 WARPS per batch, SOURCE-SPLIT matvec.
// H padded to 56. Warp w owns sources [14w,14w+14) AND (for combine)
// dest-pairs [7w,7w+7) == its own next-step sources => p round-trip
// is warp-private (__syncwarp). One __syncthreads per step for the
// cross-warp partial exchange (double-buffered).
// Phase A: lane<28 = dest pair, 14 fma2 over warp's sources.
// Phase B: lane<7 combines 4 partials, applies emit/mask/renorm.
// ============================================================
__global__ void __launch_bounds__(128, 1)
crf_scan_kernel(const float* __restrict__ transition, const float* __restrict__ masks,
                const int* __restrict__ tags) {
    const int b = blockIdx.x;
    const int tid = threadIdx.x;
    const int w = tid >> 5;
    const int lane = tid & 31;
    const int base = b * T_;
    const unsigned FULL = 0xFFFFFFFFu;

    __shared__ __align__(16) float p2[2 * HP_];          // splat pairs (p[s],p[s])
    __shared__ __align__(16) float part[2][28][8];       // [parity][dp][2w..2w+1] f32x2
    __shared__ float rslot;
    __shared__ float redsm[12];

    const float* embB = &g_emitT[(size_t)b * (H_ * T_)];

    // ---- gold score partials (reduced at the end) ----
    float gold = 0.0f, msum = 0.0f;
    for (int t = tid; t < T_; t += 128) {
        float mk = masks[base + t];
        int tg = tags[base + t];
        int pv = (t == 0) ? START_ : tags[base + t - 1];
        gold += mk * (embB[(size_t)tg * T_ + t] + transition[tg * H_ + pv]);
        msum += mk;
    }
#pragma unroll
    for (int s = 16; s > 0; s >>= 1) {
        gold += __shfl_xor_sync(FULL, gold, s);
        msum += __shfl_xor_sync(FULL, msum, s);
    }
    if (lane == 0) { redsm[w] = gold; redsm[4 + w] = msum; }

    // ---- phase-A constants: E2[k] = (expT[2dp][14w+k], expT[2dp+1][14w+k]) ----
    unsigned long long E2[14];
    const int dp = lane;           // phase-A dest pair (lane<28)
    if (lane < 28) {
        int d0 = 2 * dp, d1 = d0 + 1;
#pragma unroll
        for (int k = 0; k < 14; k++) {
            int src = 14 * w + k;
            float v0 = (d0 < H_ && src < H_) ? __expf(transition[d0 * H_ + src]) : 0.0f;
            float v1 = (d1 < H_ && src < H_) ? __expf(transition[d1 * H_ + src]) : 0.0f;
            E2[k] = pk2(v0, v1);
        }
    }

    // ---- phase-B state (lane<7): dest pair dpp = 7w+lane ----
    const int dpp = 7 * w + lane;
    const int pd0 = 2 * dpp, pd1 = pd0 + 1;
    float po0 = (pd0 == START_) ? 1.0f : 0.0f;
    float po1 = (pd1 == START_) ? 1.0f : 0.0f;
    float offset = 0.0f;
    const int c0 = (pd0 < H_) ? pd0 : 0;
    const int c1 = (pd1 < H_) ? pd1 : 0;
    const float* e0p = embB + (size_t)c0 * T_;
    const float* e1p = embB + (size_t)c1 * T_;
    const float4* m4 = reinterpret_cast<const float4*>(&masks[base]);

    float eC0[4], eC1[4], mkArr[4];
    if (lane < 7) {
        float4 a = *reinterpret_cast<const float4*>(e0p);
        float4 c = *reinterpret_cast<const float4*>(e1p);
        eC0[0] = __expf(a.x); eC0[1] = __expf(a.y); eC0[2] = __expf(a.z); eC0[3] = __expf(a.w);
        eC1[0] = __expf(c.x); eC1[1] = __expf(c.y); eC1[2] = __expf(c.z); eC1[3] = __expf(c.w);
        float4 m = m4[0];
        mkArr[0] = m.x; mkArr[1] = m.y; mkArr[2] = m.z; mkArr[3] = m.w;
    }

    // ---- init p2 splats ----
    if (tid < HP_) {
        float v = (tid == START_) ? 1.0f : 0.0f;
        p2[2 * tid] = v; p2[2 * tid + 1] = v;
    }
    __syncthreads();

    const float* pw = &p2[28 * w];   // this warp's source splats (16B-aligned)

    const int NB = T_ / 4;  // 128
    for (int tb = 0; tb < NB; tb++) {
        // prefetch next block's emit/mask (phase-B lanes only)
        float4 l0, l1, lm;
        const bool hv = (tb + 1 < NB);
        if (lane < 7 && hv) {
            l0 = *reinterpret_cast<const float4*>(e0p + (tb + 1) * 4);
            l1 = *reinterpret_cast<const float4*>(e1p + (tb + 1) * 4);
            lm = m4[tb + 1];
        }

#pragma unroll
        for (int s = 0; s < 4; s++) {
            const int par = s & 1;
            // ---- phase A ----
            if (lane < 28) {
                const ulonglong2* u = reinterpret_cast<const ulonglong2*>(pw);
                ulonglong2 u0 = u[0], u1 = u[1], u2 = u[2];
                ulonglong2 u3 = u[3], u4 = u[4], u5 = u[5], u6 = u[6];
                unsigned long long a0 = 0ULL, a1 = 0ULL, a2 = 0ULL, a3 = 0ULL;
                a0 = fma2(E2[0],  u0.x, a0); a1 = fma2(E2[1],  u0.y, a1);
                a2 = fma2(E2[2],  u1.x, a2); a3 = fma2(E2[3],  u1.y, a3);
                a0 = fma2(E2[4],  u2.x, a0); a1 = fma2(E2[5],  u2.y, a1);
                a2 = fma2(E2[6],  u3.x, a2); a3 = fma2(E2[7],  u3.y, a3);
                a0 = fma2(E2[8],  u4.x, a0); a1 = fma2(E2[9],  u4.y, a1);
                a2 = fma2(E2[10], u5.x, a2); a3 = fma2(E2[11], u5.y, a3);
                a0 = fma2(E2[12], u6.x, a0); a1 = fma2(E2[13], u6.y, a1);
                unsigned long long s2 = add2(add2(a0, a1), add2(a2, a3));
                *reinterpret_cast<unsigned long long*>(&part[par][dp][2 * w]) = s2;
            }
            __syncthreads();
            // ---- phase B ----
            if (lane < 7) {
                const ulonglong2* q = reinterpret_cast<const ulonglong2*>(&part[par][dpp][0]);
                ulonglong2 q0 = q[0], q1 = q[1];
                unsigned long long s2 = add2(add2(q0.x, q0.y), add2(q1.x, q1.y));
                float S0, S1;
                upk2(s2, S0, S1);
                bool on = (mkArr[s] > 0.5f);
                float n0 = on ? S0 * eC0[s] : po0;
                float n1 = on ? S1 * eC1[s] : po1;
                if (s == 0 && tb) {
                    float r = rslot;            // p[0] after previous step (written s==3)
                    float ri = 1.0f / r;
                    offset += __logf(r);
                    n0 *= ri; n1 *= ri;
                }
                float4 sp = make_float4(n0, n0, n1, n1);
                *reinterpret_cast<float4*>(&p2[4 * dpp]) = sp;
                if (tid == 0 && s == 3) rslot = n0;   // dpp==0 => n0 = p[0]
                po0 = n0; po1 = n1;
            }
            __syncwarp();
        }

        if (lane < 7 && hv) {
            eC0[0] = __expf(l0.x); eC0[1] = __expf(l0.y); eC0[2] = __expf(l0.z); eC0[3] = __expf(l0.w);
            eC1[0] = __expf(l1.x); eC1[1] = __expf(l1.y); eC1[2] = __expf(l1.z); eC1[3] = __expf(l1.w);
            mkArr[0] = lm.x; mkArr[1] = lm.y; mkArr[2] = lm.z; mkArr[3] = lm.w;
        }
    }

    // ---- final reduction ----
    float term = 0.0f;
    if (lane < 7) {
        float es0 = (pd0 < H_) ? __expf(transition[STOP_ * H_ + pd0]) : 0.0f;
        float es1 = (pd1 < H_) ? __expf(transition[STOP_ * H_ + pd1]) : 0.0f;
        term = po0 * es0 + po1 * es1;
    }
#pragma unroll
    for (int s = 16; s > 0; s >>= 1) term += __shfl_xor_sync(FULL, term, s);
    if (lane == 0) redsm[8 + w] = term;
    __syncthreads();
    if (tid == 0) {
        float goldv = redsm[0] + redsm[1] + redsm[2] + redsm[3];
        float msumv = redsm[4] + redsm[5] + redsm[6] + redsm[7];
        float tsum  = redsm[8] + redsm[9] + redsm[10] + redsm[11];
        int lp = (int)(msumv + 0.5f);
        int lt = (lp > 0) ? tags[base + lp - 1] : START_;
        goldv += transition[STOP_ * H_ + lt];
        g_diff[b] = offset + __logf(tsum) - goldv;
    }
}

// ============================================================
// Kernel 3: mean over batches
// ============================================================
__global__ void __launch_bounds__(64)
finalize_kernel(float* __restrict__ out) {
    __shared__ float red[64];
    int tid = threadIdx.x;
    red[tid] = g_diff[tid];
    __syncthreads();
    for (int s = 32; s > 0; s >>= 1) { if (tid < s) red[tid] += red[tid + s]; __syncthreads(); }
    if (tid == 0) out[0] = red[0] * (1.0f / (float)B_);
}

// ============================================================
// launch
// ============================================================
extern "C" void kernel_launch(void* const* d_in, const int* in_sizes, int n_in,
                              void* d_out, int out_size) {
    const float* feat  = (const float*)d_in[0];
    const float* W     = (const float*)d_in[1];
    const float* bias  = (const float*)d_in[2];
    const float* trans = (const float*)d_in[3];
    const float* masks = (const float*)d_in[4];
    const int*   tags  = (const int*)d_in[5];
    float* out = (float*)d_out;

    emit_gemm_kernel<<<128, 256>>>(feat, W, bias);
    crf_scan_kernel<<<B_, 128>>>(trans, masks, tags);
    finalize_kernel<<<1, 64>>>(out);
}